// round 14
// baseline (speedup 1.0000x reference)
#include <cuda_runtime.h>
#include <cuda_bf16.h>
#include <cstddef>

// NGCF conv: out = leaky(agg@W1+b1) + leaky((agg*feat)@W2+b2)
// where agg = scatter_add(edge_vals * feat[edge_col], edge_row)
//
// N=100000 nodes, E=1600000 edges, D_IN=D_OUT=64, all fp32.

#define N_NODES 100000
#define N_EDGES 1600000
#define D       64

// Scratch for the aggregated features.  __device__ globals are
// zero-initialized at module load, and fused_gemm_kernel re-zeroes every
// element it consumes, so every kernel_launch call starts from zeros with
// NO separate zeroing kernel.
__device__ __align__(256) float g_agg[(size_t)N_NODES * D];

// ---------------------------------------------------------------------------
// Kernel 1: edge scatter.  4 lanes per edge; each lane gathers 4 float4 from
// feat[col] (independent LDG.128s -> MLP=4), scales by edge_val, then issues
// 4x red.global.add.v4.f32 into g_agg[row].
// node_feat (25.6MB) + g_agg (25.6MB) stay L2-resident -> L2/REDG bound
// (~820MB L2 traffic at ~6300 B/cyc LTS cap).  v4 RED = 4x fewer L2 atomic
// ops than scalar atomicAdd.
// ---------------------------------------------------------------------------
__global__ __launch_bounds__(256) void scatter_kernel(
    const int*   __restrict__ erow,
    const int*   __restrict__ ecol,
    const float* __restrict__ evals,
    const float* __restrict__ feat)
{
    int tid = blockIdx.x * blockDim.x + threadIdx.x;
    int e   = tid >> 2;          // 4 lanes per edge
    if (e >= N_EDGES) return;
    int sub = tid & 3;           // lane handles float4 slots {sub, sub+4, sub+8, sub+12}

    int   row = __ldg(erow + e);   // broadcast within the 4-lane group
    int   col = __ldg(ecol + e);
    float v   = __ldg(evals + e);

    const float4* src = reinterpret_cast<const float4*>(feat + (size_t)col * D);
    // Four independent gathers in flight before any RED (MLP=4).
    float4 f0 = __ldg(src + sub);
    float4 f1 = __ldg(src + sub + 4);
    float4 f2 = __ldg(src + sub + 8);
    float4 f3 = __ldg(src + sub + 12);
    f0.x *= v; f0.y *= v; f0.z *= v; f0.w *= v;
    f1.x *= v; f1.y *= v; f1.z *= v; f1.w *= v;
    f2.x *= v; f2.y *= v; f2.z *= v; f2.w *= v;
    f3.x *= v; f3.y *= v; f3.z *= v; f3.w *= v;

    float* dst = g_agg + (size_t)row * D;
    asm volatile("red.global.add.v4.f32 [%0], {%1, %2, %3, %4};"
                 :: "l"(dst + sub * 4),
                    "f"(f0.x), "f"(f0.y), "f"(f0.z), "f"(f0.w) : "memory");
    asm volatile("red.global.add.v4.f32 [%0], {%1, %2, %3, %4};"
                 :: "l"(dst + (sub + 4) * 4),
                    "f"(f1.x), "f"(f1.y), "f"(f1.z), "f"(f1.w) : "memory");
    asm volatile("red.global.add.v4.f32 [%0], {%1, %2, %3, %4};"
                 :: "l"(dst + (sub + 8) * 4),
                    "f"(f2.x), "f"(f2.y), "f"(f2.z), "f"(f2.w) : "memory");
    asm volatile("red.global.add.v4.f32 [%0], {%1, %2, %3, %4};"
                 :: "l"(dst + (sub + 12) * 4),
                    "f"(f3.x), "f"(f3.y), "f"(f3.z), "f"(f3.w) : "memory");
}

// ---------------------------------------------------------------------------
// Kernel 2: fused dual-GEMM epilogue + agg re-zero.
//   part1 = leaky(agg @ W1 + b1)
//   part2 = leaky((agg * feat) @ W2 + b2)
//   out   = part1 + part2
//   (and g_agg[slice] = 0 for the next graph replay)
// Tile: 64 nodes x 64 outputs per 256-thread block, 64KB dynamic smem
// (W1/W2 32KB + A/AF tiles 32KB).  Halves weight-reload L2 traffic vs the
// 32-node tile (1563 blocks x 32KB = 50MB instead of 100MB).
// Each thread: 4 nodes x 4 cols x 2 GEMMs = 32 FMA per k-step.
// ---------------------------------------------------------------------------
__global__ __launch_bounds__(256) void fused_gemm_kernel(
    const float* __restrict__ feat,
    const float* __restrict__ W1,
    const float* __restrict__ b1,
    const float* __restrict__ W2,
    const float* __restrict__ b2,
    float*       __restrict__ out)
{
    extern __shared__ float smem[];
    float* W1s = smem;              // [k][j] 16 KB
    float* W2s = smem + D * D;      // [k][j] 16 KB
    float* As  = smem + 2 * D * D;  // [m][k] 16 KB (64 nodes)
    float* AFs = smem + 3 * D * D;  // [m][k] 16 KB

    const int tid  = threadIdx.x;
    const int base = blockIdx.x * 64;

    // Load weights (row-major [D_IN][D_OUT] == [k][j])
    #pragma unroll
    for (int i = tid; i < D * D; i += 256) {
        W1s[i] = W1[i];
        W2s[i] = W2[i];
    }

    // Load activation tiles: 64 nodes x 64 feats, coalesced.
    // Re-zero g_agg as we consume it (same thread reads then writes -> safe;
    // blocks own disjoint node slices).
    #pragma unroll
    for (int i = tid; i < 64 * D; i += 256) {
        int m    = i >> 6;
        int k    = i & 63;
        int node = base + m;
        float a = 0.f, f = 0.f;
        if (node < N_NODES) {
            size_t off = (size_t)node * D + k;
            a = g_agg[off];
            g_agg[off] = 0.f;       // ready for next replay
            f = feat[off];
        }
        As[i]  = a;
        AFs[i] = a * f;
    }
    __syncthreads();

    const int tx = tid & 15;       // 16 col-groups
    const int ty = tid >> 4;       // 16 row-groups
    const int j0 = tx * 4;         // 4 output columns per thread
    const int m0 = ty * 4;         // 4 nodes per thread

    float acc1[4][4] = {};
    float acc2[4][4] = {};

    #pragma unroll 4
    for (int k = 0; k < D; k++) {
        float4 w1 = *reinterpret_cast<const float4*>(&W1s[k * D + j0]);
        float4 w2 = *reinterpret_cast<const float4*>(&W2s[k * D + j0]);
        #pragma unroll
        for (int mi = 0; mi < 4; mi++) {
            float a = As [(m0 + mi) * D + k];
            float f = AFs[(m0 + mi) * D + k];
            acc1[mi][0] += a * w1.x; acc1[mi][1] += a * w1.y;
            acc1[mi][2] += a * w1.z; acc1[mi][3] += a * w1.w;
            acc2[mi][0] += f * w2.x; acc2[mi][1] += f * w2.y;
            acc2[mi][2] += f * w2.z; acc2[mi][3] += f * w2.w;
        }
    }

    // Bias (tiny, L1/L2 cached)
    float4 bb1 = *reinterpret_cast<const float4*>(&b1[j0]);
    float4 bb2 = *reinterpret_cast<const float4*>(&b2[j0]);
    float bias1[4] = {bb1.x, bb1.y, bb1.z, bb1.w};
    float bias2[4] = {bb2.x, bb2.y, bb2.z, bb2.w};

    #pragma unroll
    for (int mi = 0; mi < 4; mi++) {
        int node = base + m0 + mi;
        if (node >= N_NODES) continue;
        float4 r;
        float* rp = &r.x;
        #pragma unroll
        for (int jj = 0; jj < 4; jj++) {
            float x1 = acc1[mi][jj] + bias1[jj];
            float x2 = acc2[mi][jj] + bias2[jj];
            x1 = (x1 >= 0.f) ? x1 : 0.2f * x1;
            x2 = (x2 >= 0.f) ? x2 : 0.2f * x2;
            rp[jj] = x1 + x2;
        }
        *reinterpret_cast<float4*>(out + (size_t)node * D + j0) = r;
    }
}

// ---------------------------------------------------------------------------
// Launch
// ---------------------------------------------------------------------------
extern "C" void kernel_launch(void* const* d_in, const int* in_sizes, int n_in,
                              void* d_out, int out_size)
{
    const int*   erow  = (const int*)  d_in[0];
    const int*   ecol  = (const int*)  d_in[1];
    const float* evals = (const float*)d_in[2];
    const float* feat  = (const float*)d_in[3];
    const float* W1    = (const float*)d_in[4];
    const float* b1    = (const float*)d_in[5];
    const float* W2    = (const float*)d_in[6];
    const float* b2    = (const float*)d_in[7];
    float*       out   = (float*)d_out;

    // Opt-in to 64KB dynamic smem.  Unconditional every call (no static
    // guards per harness rules); cudaFuncSetAttribute is not a stream op,
    // so it is graph-capture safe and idempotent.
    cudaFuncSetAttribute(fused_gemm_kernel,
                         cudaFuncAttributeMaxDynamicSharedMemorySize,
                         64 * 1024);

    // 1) edge scatter (4 lanes per edge, 4 float4 each)
    {
        long long threads = (long long)N_EDGES * 4;
        int grid = (int)((threads + 255) / 256);
        scatter_kernel<<<grid, 256>>>(erow, ecol, evals, feat);
    }
    // 2) fused dual-GEMM epilogue (also re-zeroes g_agg for next replay)
    {
        int grid = (N_NODES + 63) / 64;
        fused_gemm_kernel<<<grid, 256, 64 * 1024>>>(feat, W1, b1, W2, b2, out);
    }
}